// round 2
// baseline (speedup 1.0000x reference)
#include <cuda_runtime.h>
#include <cstdint>
#include <cstddef>

#define DIM_K 4096      // in_features
#define DIM_N 4096      // out_features
#define DIM_M 8192      // B*S

// ---------------- scratch (static device arrays; no allocation) ----------------
__device__ __align__(256) float g_cn[DIM_K];             // column L1 norms
__device__ __align__(256) float g_mask[DIM_K];           // 1.0 = binarized column
__device__ float g_nbin;
__device__ __align__(256) float g_wbin[(size_t)DIM_N * DIM_K];  // tf32-rounded w_bin

__device__ __forceinline__ uint32_t smem_u32(const void* p) {
    uint32_t a;
    asm("{ .reg .u64 t; cvta.to.shared.u64 t, %1; cvt.u32.u64 %0, t; }" : "=r"(a) : "l"(p));
    return a;
}
__device__ __forceinline__ float tf32_rna(float v) {
    uint32_t r; asm("cvt.rna.tf32.f32 %0, %1;" : "=r"(r) : "f"(v));
    return __uint_as_float(r);
}
__device__ __forceinline__ uint32_t tf32_rna_u(uint32_t v) {
    uint32_t r; asm("cvt.rna.tf32.f32 %0, %1;" : "=r"(r) : "f"(__uint_as_float(v)));
    return r;
}

// ================= preprocessing =================

// Strict sequential fp32 column L1 norms (best-effort match of XLA order).
__global__ void k_colnorm(const float* __restrict__ w) {
    int j = blockIdx.x * 256 + threadIdx.x;
    const float* p = w + j;
    float s = 0.f;
    for (int i = 0; i < DIM_K; ++i) s += fabsf(p[(size_t)i * DIM_K]);
    g_cn[j] = s;
}

// Single block: bitonic sort, quantiles, band mask, n_bin.
__global__ void k_quant() {
    __shared__ float s_sorted[DIM_K];
    __shared__ float s_lo, s_hi;
    __shared__ int s_cnt;
    int t = threadIdx.x;  // 1024 threads

#pragma unroll
    for (int c = 0; c < 4; ++c) s_sorted[c * 1024 + t] = g_cn[c * 1024 + t];
    if (t == 0) s_cnt = 0;
    __syncthreads();

    for (int k = 2; k <= DIM_K; k <<= 1) {
        for (int jj = k >> 1; jj > 0; jj >>= 1) {
#pragma unroll
            for (int c = 0; c < 4; ++c) {
                int i = c * 1024 + t;
                int ixj = i ^ jj;
                if (ixj > i) {
                    float a = s_sorted[i], b = s_sorted[ixj];
                    bool up = ((i & k) == 0);
                    if ((a > b) == up) { s_sorted[i] = b; s_sorted[ixj] = a; }
                }
            }
            __syncthreads();
        }
    }

    if (t == 0) {
        // jnp.quantile 'linear': 0.05*4095 = 204.75; 0.95*4095 = 3890.25
        s_lo = s_sorted[204]  + 0.75f * (s_sorted[205]  - s_sorted[204]);
        s_hi = s_sorted[3890] + 0.25f * (s_sorted[3891] - s_sorted[3890]);
    }
    __syncthreads();

    int local = 0;
#pragma unroll
    for (int c = 0; c < 4; ++c) {
        int j = c * 1024 + t;
        float v = g_cn[j];
        bool band = (v > s_lo) && (v < s_hi);   // middle band
        float m = band ? 0.f : 1.f;             // binarized = ~band
        g_mask[j] = m;
        local += (int)m;
    }
    atomicAdd(&s_cnt, local);
    __syncthreads();
    if (t == 0) g_nbin = (float)s_cnt;
}

// Per row: scale = sum(|w|*mask)/n_bin; w_bin = mask ? w*scale : w (tf32 RNA-rounded).
__global__ void k_wbin(const float* __restrict__ w) {
    __shared__ float red[256];
    __shared__ float s_scale;
    int r = blockIdx.x, t = threadIdx.x;
    const float* wr = w + (size_t)r * DIM_K;

    float s = 0.f;
    for (int j = t; j < DIM_K; j += 256) s += fabsf(wr[j]) * g_mask[j];
    red[t] = s;
    __syncthreads();
    for (int o = 128; o > 0; o >>= 1) {
        if (t < o) red[t] += red[t + o];
        __syncthreads();
    }
    if (t == 0) s_scale = red[0] / g_nbin;
    __syncthreads();
    float scale = s_scale;

    float* dst = g_wbin + (size_t)r * DIM_K;
    for (int j = t; j < DIM_K; j += 256) {
        float v = wr[j];
        float o = (g_mask[j] != 0.f) ? v * scale : v;
        dst[j] = tf32_rna(o);
    }
}

// ================= GEMM: out = x @ w_bin^T + bias (mma.sync tf32) =================
#define BM 128
#define BN 128
#define BK 32                       // 32 tf32 = 128 B rows (SW128 atom)
#define KTILES (DIM_K / BK)         // 128
#define STAGES 3
#define STAGE_BYTES 32768           // A(16KB) + B(16KB)
#define GEMM_SMEM (STAGES * STAGE_BYTES)

__device__ __forceinline__ void cp16(uint32_t dst, const void* src) {
    asm volatile("cp.async.cg.shared.global [%0], [%1], 16;" :: "r"(dst), "l"(src));
}
__device__ __forceinline__ void ldm_x4(uint32_t* r, uint32_t addr) {
    asm volatile("ldmatrix.sync.aligned.m8n8.x4.shared.b16 {%0,%1,%2,%3}, [%4];"
                 : "=r"(r[0]), "=r"(r[1]), "=r"(r[2]), "=r"(r[3]) : "r"(addr));
}
__device__ __forceinline__ void mma_tf32(float* c, const uint32_t* a,
                                         uint32_t b0, uint32_t b1) {
    asm volatile(
        "mma.sync.aligned.m16n8k8.row.col.f32.tf32.tf32.f32 "
        "{%0,%1,%2,%3}, {%4,%5,%6,%7}, {%8,%9}, {%0,%1,%2,%3};"
        : "+f"(c[0]), "+f"(c[1]), "+f"(c[2]), "+f"(c[3])
        : "r"(a[0]), "r"(a[1]), "r"(a[2]), "r"(a[3]), "r"(b0), "r"(b1));
}

__global__ void __launch_bounds__(256, 2) k_gemm(
    const float* __restrict__ x, const float* __restrict__ bias, float* __restrict__ out)
{
    extern __shared__ char smem[];
    const uint32_t sb = smem_u32(smem);
    const int tid = threadIdx.x;
    const int wid = tid >> 5;
    const int lane = tid & 31;
    const int warp_m = wid >> 2;   // 0..1
    const int warp_n = wid & 3;    // 0..3
    const int ntile = blockIdx.x;
    const int mtile = blockIdx.y;

    const float* gA = x      + (size_t)mtile * BM * DIM_K;
    const float* gB = g_wbin + (size_t)ntile * BN * DIM_K;

    // loader mapping: idx = pass*256+tid; row = idx>>3 (0..127), 16B chunk = idx&7
    const int lrow = tid >> 3;          // base row for pass stride 32
    const int lc   = tid & 7;           // 16B chunk
    uint32_t ld_swz[4];
#pragma unroll
    for (int p = 0; p < 4; ++p) {
        int row = lrow + p * 32;
        ld_swz[p] = (uint32_t)(row * 128 + ((lc * 16) ^ ((row & 7) << 4)));
    }

    // ldmatrix lane address components
    const uint32_t sx = (uint32_t)((lane & 7) << 4);
    const int arow = warp_m * 64 + (lane & 15);          // + mt*16
    const uint32_t acol16 = (lane & 16) ? 16u : 0u;
    const int brow = warp_n * 32 + (lane & 7) + ((lane & 16) ? 8 : 0);  // + nt16*16
    const uint32_t bcol16 = (lane & 8) ? 16u : 0u;

    float acc[4][4][4];
#pragma unroll
    for (int i = 0; i < 4; ++i)
#pragma unroll
        for (int j = 0; j < 4; ++j)
#pragma unroll
            for (int k = 0; k < 4; ++k) acc[i][j][k] = 0.f;

    // ---- pipeline ----
    auto load_stage = [&](int s, int kt) {
        uint32_t sA = sb + s * STAGE_BYTES;
        uint32_t sB = sA + 16384;
#pragma unroll
        for (int p = 0; p < 4; ++p) {
            int row = lrow + p * 32;
            const float* srcA = gA + (size_t)row * DIM_K + kt * BK + lc * 4;
            cp16(sA + ld_swz[p], srcA);
        }
#pragma unroll
        for (int p = 0; p < 4; ++p) {
            int row = lrow + p * 32;
            const float* srcB = gB + (size_t)row * DIM_K + kt * BK + lc * 4;
            cp16(sB + ld_swz[p], srcB);
        }
    };

#pragma unroll
    for (int s = 0; s < STAGES - 1; ++s) {
        load_stage(s, s);
        asm volatile("cp.async.commit_group;" ::: "memory");
    }

    for (int kt = 0; kt < KTILES; ++kt) {
        asm volatile("cp.async.wait_group 1;" ::: "memory");
        __syncthreads();

        if (kt + STAGES - 1 < KTILES) load_stage((kt + STAGES - 1) % STAGES, kt + STAGES - 1);
        asm volatile("cp.async.commit_group;" ::: "memory");

        const int s = kt % STAGES;
        const uint32_t sA = sb + s * STAGE_BYTES;
        const uint32_t sB = sA + 16384;

#pragma unroll
        for (int ks = 0; ks < 4; ++ks) {
            uint32_t bfr[8];
            {
                uint32_t col = (uint32_t)(ks * 32) + bcol16;
                uint32_t a0 = sB + (uint32_t)(brow * 128) + (col ^ sx);
                uint32_t a1 = sB + (uint32_t)((brow + 16) * 128) + (col ^ sx);
                ldm_x4(bfr + 0, a0);
                ldm_x4(bfr + 4, a1);
            }
#pragma unroll
            for (int mt = 0; mt < 4; ++mt) {
                uint32_t afr[4];
                uint32_t col = (uint32_t)(ks * 32) + acol16;
                uint32_t aad = sA + (uint32_t)((arow + mt * 16) * 128) + (col ^ sx);
                ldm_x4(afr, aad);
                afr[0] = tf32_rna_u(afr[0]); afr[1] = tf32_rna_u(afr[1]);
                afr[2] = tf32_rna_u(afr[2]); afr[3] = tf32_rna_u(afr[3]);
                mma_tf32(acc[mt][0], afr, bfr[0], bfr[1]);
                mma_tf32(acc[mt][1], afr, bfr[2], bfr[3]);
                mma_tf32(acc[mt][2], afr, bfr[4], bfr[5]);
                mma_tf32(acc[mt][3], afr, bfr[6], bfr[7]);
            }
        }
    }

    // ---- epilogue: add bias, store fp32 ----
    const int obase_n = ntile * BN + warp_n * 32;
#pragma unroll
    for (int mt = 0; mt < 4; ++mt) {
        int row0 = mtile * BM + warp_m * 64 + mt * 16 + (lane >> 2);
#pragma unroll
        for (int nt = 0; nt < 4; ++nt) {
            int col = obase_n + nt * 8 + (lane & 3) * 2;
            float b0 = __ldg(bias + col);
            float b1 = __ldg(bias + col + 1);
            float2 v0 = make_float2(acc[mt][nt][0] + b0, acc[mt][nt][1] + b1);
            float2 v1 = make_float2(acc[mt][nt][2] + b0, acc[mt][nt][3] + b1);
            *(float2*)(out + (size_t)row0 * DIM_N + col) = v0;
            *(float2*)(out + (size_t)(row0 + 8) * DIM_N + col) = v1;
        }
    }
}

// ================= launch =================
extern "C" void kernel_launch(void* const* d_in, const int* in_sizes, int n_in,
                              void* d_out, int out_size) {
    const float* x    = (const float*)d_in[0];   // [8192, 4096]
    const float* w    = (const float*)d_in[1];   // [4096, 4096]
    const float* bias = (const float*)d_in[2];   // [4096]
    float* out = (float*)d_out;                  // [8192, 4096]

    cudaFuncSetAttribute(k_gemm, cudaFuncAttributeMaxDynamicSharedMemorySize, GEMM_SMEM);

    k_colnorm<<<DIM_K / 256, 256>>>(w);
    k_quant<<<1, 1024>>>();
    k_wbin<<<DIM_N, 256>>>(w);
    k_gemm<<<dim3(DIM_N / BN, DIM_M / BM), 256, GEMM_SMEM>>>(x, bias, out);
}